// round 14
// baseline (speedup 1.0000x reference)
#include <cuda_runtime.h>
#include <cuda_fp16.h>
#include <cstring>

#define B_    2
#define C_    32
#define H_    128
#define W_    256
#define MAXD  12
#define D_    23            // 2*MAXD - 1
#define HW    (H_ * W_)
#define WT    128           // threads per CTA (half row)
#define NO    4             // channel octs of 8
#define SW2   220           // window: 76 left halo + 128 + 16 right
#define HALO  76

__device__ __forceinline__ __half2 u2h2(unsigned u) {
    __half2 r; memcpy(&r, &u, 4); return r;
}

// Mainloop for one disparity group: DLO = first disparity, DGv = count.
// Gather = (DGv+1) x LDS.128 per oct; math identical op-order to R11;
// half2 accumulators flushed to fp32 every 2 octs (8 |terms| per half lane,
// magnitude ~9 -> rel_err ~2.5e-4, tol 1e-3).
template<int DLO, int DGv>
__device__ __forceinline__ void run_group(
    const uint4 (*s_o)[SW2], int xs,
    __half2 nw0, __half2 nw1,
    const float* __restrict__ fl0,
    float* __restrict__ orow)
{
    constexpr int TAPSv = DGv + 1;

    float accf[DGv];
    __half2 acc2[DGv];
    #pragma unroll
    for (int d = 0; d < DGv; d++) { accf[d] = 0.0f; acc2[d] = __float2half2_rn(0.0f); }

    #pragma unroll 1
    for (int o = 0; o < NO; o++) {                 // 4 octs (8 channels each)
        const float a0 = __ldg(fl0 + (2*o)      * HW);
        const float a1 = __ldg(fl0 + (2*o + 1)  * HW);
        const float a2 = __ldg(fl0 + (2*o + 16) * HW);
        const float a3 = __ldg(fl0 + (2*o + 17) * HW);
        const float b0 = __ldg(fl0 + (2*o + 8)  * HW);
        const float b1 = __ldg(fl0 + (2*o + 9)  * HW);
        const float b2 = __ldg(fl0 + (2*o + 24) * HW);
        const float b3 = __ldg(fl0 + (2*o + 25) * HW);
        const __half2 fX = __floats2half2_rn(a0, a2);
        const __half2 fY = __floats2half2_rn(a1, a3);
        const __half2 fZ = __floats2half2_rn(b0, b2);
        const __half2 fW = __floats2half2_rn(b1, b3);

        const uint4* row = &s_o[o][xs];
        uint4 t[TAPSv];
        #pragma unroll
        for (int j = 0; j < TAPSv; j++) t[j] = row[j];   // LDS.128

        #pragma unroll
        for (int d = 0; d < DGv; d++) {
            __half2 u0 = __hfma2(u2h2(t[d].x),     nw0, fX);
            u0         = __hfma2(u2h2(t[d + 1].x), nw1, u0);
            __half2 u1 = __hfma2(u2h2(t[d].y),     nw0, fY);
            u1         = __hfma2(u2h2(t[d + 1].y), nw1, u1);
            __half2 u2 = __hfma2(u2h2(t[d].z),     nw0, fZ);
            u2         = __hfma2(u2h2(t[d + 1].z), nw1, u2);
            __half2 u3 = __hfma2(u2h2(t[d].w),     nw0, fW);
            u3         = __hfma2(u2h2(t[d + 1].w), nw1, u3);
            __half2 s01 = __hadd2(__habs2(u0), __habs2(u1));
            __half2 s23 = __hadd2(__habs2(u2), __habs2(u3));
            acc2[d] = __hadd2(acc2[d], __hadd2(s01, s23));
        }

        // flush packed half accumulators to fp32 every 2 octs (16 channels)
        if (o & 1) {
            #pragma unroll
            for (int d = 0; d < DGv; d++) {
                float2 f = __half22float2(acc2[d]);
                accf[d] += f.x + f.y;
                acc2[d] = __float2half2_rn(0.0f);
            }
        }
    }

    #pragma unroll
    for (int d = 0; d < DGv; d++)
        orow[(long)d * HW] = accf[d];
}

// out[b,d,h,w] = sum_c |feat_l[b,c,h,w] - (w0*fr[c,x0+d] + w1*fr[c,x0+d+1])|
// R11 scaffold (fp16 8-channel octs, LDS.128 gather, 1024 thin CTAs of 128
// threads) with two pure instruction-count reductions (the kernel is now
// issue-bound, not crossbar-bound): (1) asymmetric d-splits 12/11 via a
// compile-time branch, removing the duplicated d=11 compute; (2) fp32 flush
// every 2 octs instead of every oct. No sort / pipeline / hoist (all
// measured regressions).
__global__ __launch_bounds__(WT)
void cost_volume_kernel(const float* __restrict__ feat_l,
                        const float* __restrict__ feat_r,
                        const float* __restrict__ disp,
                        float* __restrict__ out)
{
    __shared__ __align__(16) uint4 s_o[NO][SW2];   // 14080 B

    const int xb    = blockIdx.x;        // 0..3 : (spl<<1)|half
    const int half_ = xb & 1;
    const int spl   = xb >> 1;
    const int h     = blockIdx.y;
    const int b     = blockIdx.z;
    const int tid   = threadIdx.x;
    const int W0    = half_ * WT;
    const int base  = W0 - HALO;         // global x of window index 0

    // ---- stage zero-padded feat_r window as 8-channel octs (R11 fill) ----
    {
        const float* fr0 = feat_r + (((long)b * C_) * H_ + h) * W_;
        #pragma unroll
        for (int s = 0; s < 2; s++) {
            const int i = tid + s * WT;
            if (i < SW2) {
                const int gx = base + i;
                const bool v = (gx >= 0) & (gx < W_);
                const int gxc = v ? gx : 0;
                #pragma unroll
                for (int o = 0; o < NO; o++) {
                    const float a0 = v ? __ldg(fr0 + (2*o)      * HW + gxc) : 0.0f;
                    const float a1 = v ? __ldg(fr0 + (2*o + 1)  * HW + gxc) : 0.0f;
                    const float a2 = v ? __ldg(fr0 + (2*o + 16) * HW + gxc) : 0.0f;
                    const float a3 = v ? __ldg(fr0 + (2*o + 17) * HW + gxc) : 0.0f;
                    const float b0 = v ? __ldg(fr0 + (2*o + 8)  * HW + gxc) : 0.0f;
                    const float b1 = v ? __ldg(fr0 + (2*o + 9)  * HW + gxc) : 0.0f;
                    const float b2 = v ? __ldg(fr0 + (2*o + 24) * HW + gxc) : 0.0f;
                    const float b3 = v ? __ldg(fr0 + (2*o + 25) * HW + gxc) : 0.0f;
                    __half2 px = __floats2half2_rn(a0, a2);
                    __half2 py = __floats2half2_rn(a1, a3);
                    __half2 pz = __floats2half2_rn(b0, b2);
                    __half2 pw = __floats2half2_rn(b1, b3);
                    uint4 ov;
                    memcpy(&ov.x, &px, 4); memcpy(&ov.y, &py, 4);
                    memcpy(&ov.z, &pz, 4); memcpy(&ov.w, &pw, 4);
                    s_o[o][i] = ov;
                }
            }
        }
    }

    // ---- per-thread interpolation setup (overlaps fill) ----
    const int   w    = W0 + tid;
    const float dval = __ldg(disp + ((long)b * H_ + h) * W_ + w);
    const float px0  = ((float)w - dval) - (float)(MAXD - 1);
    const float xf   = floorf(px0);
    const float w1   = px0 - xf;          // right-neighbor weight (const over d)
    const float w0   = 1.0f - w1;
    int x0l = (int)xf - base;             // in [tid+1, tid+65]
    x0l = max(0, min(SW2 - 24, x0l));     // x0l + 23 <= 219

    const __half2 nw0 = __float2half2_rn(-w0);
    const __half2 nw1 = __float2half2_rn(-w1);

    __syncthreads();

    const float* fl0 = feat_l + (((long)b * C_) * H_ + h) * W_ + w;

    if (spl == 0) {
        // disparities 0..11 (13 taps)
        float* orow = out + (((long)b * D_ + 0) * H_ + h) * W_ + w;
        run_group<0, 12>(s_o, x0l, nw0, nw1, fl0, orow);
    } else {
        // disparities 12..22 (12 taps) — no duplicate d=11
        float* orow = out + (((long)b * D_ + 12) * H_ + h) * W_ + w;
        run_group<12, 11>(s_o, x0l + 12, nw0, nw1, fl0, orow);
    }
}

extern "C" void kernel_launch(void* const* d_in, const int* in_sizes, int n_in,
                              void* d_out, int out_size)
{
    (void)in_sizes; (void)n_in; (void)out_size;
    const float* feat_l = (const float*)d_in[0];
    const float* feat_r = (const float*)d_in[1];
    const float* disp   = (const float*)d_in[2];
    float* out = (float*)d_out;

    dim3 grid(4, H_, B_);     // 2 halves x 2 d-splits = 1024 thin CTAs
    cost_volume_kernel<<<grid, WT>>>(feat_l, feat_r, disp, out);
}

// round 15
// speedup vs baseline: 1.0172x; 1.0172x over previous
#include <cuda_runtime.h>
#include <cuda_fp16.h>
#include <cstring>

#define B_    2
#define C_    32
#define H_    128
#define W_    256
#define MAXD  12
#define D_    23            // 2*MAXD - 1
#define HW    (H_ * W_)
#define WT    128           // threads per CTA (half row)
#define NO    4             // channel octs of 8
#define SW2   220           // window: 76 left halo + 128 + 16 right
#define HALO  76
#define DG    12            // disparities per split (d=11 computed by both)
#define TAPS  13            // DG + 1

__device__ __forceinline__ __half2 u2h2(unsigned u) {
    __half2 r; memcpy(&r, &u, 4); return r;
}

struct FlcRaw { float a0, a1, a2, a3, b0, b1, b2, b3; };

__device__ __forceinline__ FlcRaw load_flc(const float* __restrict__ fl0, int o) {
    FlcRaw f;
    f.a0 = __ldg(fl0 + (2*o)      * HW);
    f.a1 = __ldg(fl0 + (2*o + 1)  * HW);
    f.a2 = __ldg(fl0 + (2*o + 16) * HW);
    f.a3 = __ldg(fl0 + (2*o + 17) * HW);
    f.b0 = __ldg(fl0 + (2*o + 8)  * HW);
    f.b1 = __ldg(fl0 + (2*o + 9)  * HW);
    f.b2 = __ldg(fl0 + (2*o + 24) * HW);
    f.b3 = __ldg(fl0 + (2*o + 25) * HW);
    return f;
}

// out[b,d,h,w] = sum_c |feat_l[b,c,h,w] - (w0*fr[c,x0+d] + w1*fr[c,x0+d+1])|
// R11 exactly (fp16 8-channel octs, 13 x LDS.128 gather, 1024 thin CTAs,
// symmetric d-splits 0/11, flush every oct) + ONE change: feat_l for oct
// o+1 is prefetched while oct o's math runs (distance-1, 8 LDG.32, +8 regs),
// removing the per-oct LDG->cvt->HFMA head stall (~4x200 cyc exposed L2
// latency) that R12-R14 showed is the remaining binder. LDS path untouched.
__global__ __launch_bounds__(WT)
void cost_volume_kernel(const float* __restrict__ feat_l,
                        const float* __restrict__ feat_r,
                        const float* __restrict__ disp,
                        float* __restrict__ out)
{
    __shared__ __align__(16) uint4 s_o[NO][SW2];   // 14080 B

    const int xb    = blockIdx.x;        // 0..3 : (spl<<1)|half
    const int half_ = xb & 1;
    const int spl   = xb >> 1;
    const int h     = blockIdx.y;
    const int b     = blockIdx.z;
    const int tid   = threadIdx.x;
    const int W0    = half_ * WT;
    const int base  = W0 - HALO;         // global x of window index 0
    const int dlo   = spl * 11;          // 0 or 11

    // ---- stage zero-padded feat_r window as 8-channel octs (R11 fill) ----
    {
        const float* fr0 = feat_r + (((long)b * C_) * H_ + h) * W_;
        #pragma unroll
        for (int s = 0; s < 2; s++) {
            const int i = tid + s * WT;
            if (i < SW2) {
                const int gx = base + i;
                const bool v = (gx >= 0) & (gx < W_);
                const int gxc = v ? gx : 0;
                #pragma unroll
                for (int o = 0; o < NO; o++) {
                    const float a0 = v ? __ldg(fr0 + (2*o)      * HW + gxc) : 0.0f;
                    const float a1 = v ? __ldg(fr0 + (2*o + 1)  * HW + gxc) : 0.0f;
                    const float a2 = v ? __ldg(fr0 + (2*o + 16) * HW + gxc) : 0.0f;
                    const float a3 = v ? __ldg(fr0 + (2*o + 17) * HW + gxc) : 0.0f;
                    const float b0 = v ? __ldg(fr0 + (2*o + 8)  * HW + gxc) : 0.0f;
                    const float b1 = v ? __ldg(fr0 + (2*o + 9)  * HW + gxc) : 0.0f;
                    const float b2 = v ? __ldg(fr0 + (2*o + 24) * HW + gxc) : 0.0f;
                    const float b3 = v ? __ldg(fr0 + (2*o + 25) * HW + gxc) : 0.0f;
                    __half2 px = __floats2half2_rn(a0, a2);
                    __half2 py = __floats2half2_rn(a1, a3);
                    __half2 pz = __floats2half2_rn(b0, b2);
                    __half2 pw = __floats2half2_rn(b1, b3);
                    uint4 ov;
                    memcpy(&ov.x, &px, 4); memcpy(&ov.y, &py, 4);
                    memcpy(&ov.z, &pz, 4); memcpy(&ov.w, &pw, 4);
                    s_o[o][i] = ov;
                }
            }
        }
    }

    // ---- per-thread interpolation setup (overlaps fill) ----
    const int   w    = W0 + tid;
    const float dval = __ldg(disp + ((long)b * H_ + h) * W_ + w);
    const float px0  = ((float)w - dval) - (float)(MAXD - 1);
    const float xf   = floorf(px0);
    const float w1   = px0 - xf;          // right-neighbor weight (const over d)
    const float w0   = 1.0f - w1;
    int x0l = (int)xf - base;             // in [tid+1, tid+65]
    x0l = max(0, min(SW2 - 24, x0l));     // xs + 12 <= 219 for both splits
    const int xs = x0l + dlo;

    const __half2 nw0 = __float2half2_rn(-w0);
    const __half2 nw1 = __float2half2_rn(-w1);

    const float* fl0 = feat_l + (((long)b * C_) * H_ + h) * W_ + w;

    // prime the feat_l pipeline (8 LDGs in flight across the barrier)
    FlcRaw cur = load_flc(fl0, 0);

    __syncthreads();

    float accf[DG];
    #pragma unroll
    for (int d = 0; d < DG; d++) accf[d] = 0.0f;

    #pragma unroll 1
    for (int o = 0; o < NO; o++) {                 // 4 octs (8 channels each)
        // prefetch next oct's feat_l while this oct's math runs
        FlcRaw nxt;
        if (o < NO - 1) nxt = load_flc(fl0, o + 1);

        const __half2 fX = __floats2half2_rn(cur.a0, cur.a2);
        const __half2 fY = __floats2half2_rn(cur.a1, cur.a3);
        const __half2 fZ = __floats2half2_rn(cur.b0, cur.b2);
        const __half2 fW = __floats2half2_rn(cur.b1, cur.b3);

        const uint4* row = &s_o[o][xs];
        uint4 t[TAPS];
        #pragma unroll
        for (int j = 0; j < TAPS; j++) t[j] = row[j];   // 13 x LDS.128

        __half2 acc2[DG];
        #pragma unroll
        for (int d = 0; d < DG; d++) acc2[d] = __float2half2_rn(0.0f);

        #pragma unroll
        for (int d = 0; d < DG; d++) {
            __half2 u0 = __hfma2(u2h2(t[d].x),     nw0, fX);
            u0         = __hfma2(u2h2(t[d + 1].x), nw1, u0);
            __half2 u1 = __hfma2(u2h2(t[d].y),     nw0, fY);
            u1         = __hfma2(u2h2(t[d + 1].y), nw1, u1);
            __half2 u2 = __hfma2(u2h2(t[d].z),     nw0, fZ);
            u2         = __hfma2(u2h2(t[d + 1].z), nw1, u2);
            __half2 u3 = __hfma2(u2h2(t[d].w),     nw0, fW);
            u3         = __hfma2(u2h2(t[d + 1].w), nw1, u3);
            __half2 s01 = __hadd2(__habs2(u0), __habs2(u1));
            __half2 s23 = __hadd2(__habs2(u2), __habs2(u3));
            acc2[d] = __hadd2(acc2[d], __hadd2(s01, s23));
        }

        // flush packed half accumulators to fp32 (every oct, as R11)
        #pragma unroll
        for (int d = 0; d < DG; d++) {
            float2 f = __half22float2(acc2[d]);
            accf[d] += f.x + f.y;
        }

        cur = nxt;
    }

    // ---- write out[b, dlo+d, h, w] (d=11 written by both splits, same value) ----
    float* orow = out + (((long)b * D_ + dlo) * H_ + h) * W_ + w;
    #pragma unroll
    for (int d = 0; d < DG; d++)
        orow[(long)d * HW] = accf[d];
}

extern "C" void kernel_launch(void* const* d_in, const int* in_sizes, int n_in,
                              void* d_out, int out_size)
{
    (void)in_sizes; (void)n_in; (void)out_size;
    const float* feat_l = (const float*)d_in[0];
    const float* feat_r = (const float*)d_in[1];
    const float* disp   = (const float*)d_in[2];
    float* out = (float*)d_out;

    dim3 grid(4, H_, B_);     // 2 halves x 2 d-splits = 1024 thin CTAs
    cost_volume_kernel<<<grid, WT>>>(feat_l, feat_r, disp, out);
}